// round 16
// baseline (speedup 1.0000x reference)
#include <cuda_runtime.h>
#include <math.h>

// ---------------------------------------------------------------------------
// FINAL kernel (R15 champion + 128-thread blocks).
// Architecture settled over 15 rounds: 8 points/thread, 3 front-batched
// LDG.256 (L2::evict_last) issued BEFORE the pose barrier (loads are
// independent of R|t; starts the memory stream ~200cyc earlier per block),
// 24 FMA triplets, 3 STG.256 (L2::evict_first), flat one-shot grid, fused
// fp32 SE(3) exp map broadcast via smem.
// R16 micro-opt: 128-thread blocks (8193 of them) — barrier spans 4 warps
// instead of 8 (tighter arrival spread), finer scheduling granularity.
// Steady-state floor: 192MB compulsory traffic at ~5.8TB/s + ~2us overhead.
// ---------------------------------------------------------------------------
struct V8 { unsigned r0, r1, r2, r3, r4, r5, r6, r7; };

__device__ __forceinline__ V8 ldg256_el(const void* p) {
    V8 v;
    asm volatile("ld.global.nc.L2::evict_last.v8.b32 "
                 "{%0,%1,%2,%3,%4,%5,%6,%7}, [%8];"
                 : "=r"(v.r0), "=r"(v.r1), "=r"(v.r2), "=r"(v.r3),
                   "=r"(v.r4), "=r"(v.r5), "=r"(v.r6), "=r"(v.r7)
                 : "l"(p));
    return v;
}
__device__ __forceinline__ void stg256_ef(void* p, const float* g) {
    asm volatile("st.global.L2::evict_first.v8.b32 "
                 "[%0], {%1,%2,%3,%4,%5,%6,%7,%8};"
                 :: "l"(p),
                    "r"(__float_as_uint(g[0])), "r"(__float_as_uint(g[1])),
                    "r"(__float_as_uint(g[2])), "r"(__float_as_uint(g[3])),
                    "r"(__float_as_uint(g[4])), "r"(__float_as_uint(g[5])),
                    "r"(__float_as_uint(g[6])), "r"(__float_as_uint(g[7]))
                 : "memory");
}

#define NTHREADS 128

__global__ void __launch_bounds__(NTHREADS)
se3_fused_kernel(const float* __restrict__ pose,
                 const char* __restrict__ xb, char* __restrict__ ob,
                 int n_oct,
                 const float* __restrict__ x_tail, float* __restrict__ o_tail,
                 int n_tail) {
    __shared__ float sRt[12];

    const int i = blockIdx.x * blockDim.x + threadIdx.x;
    const bool body = (i < n_oct);

    // ---- 1. Issue the 3 x 256-bit loads FIRST (independent of R|t). ----
    V8 a, b, c;
    if (body) {
        const char* p = xb + (size_t)96 * i;
        a = ldg256_el(p);
        b = ldg256_el(p + 32);
        c = ldg256_el(p + 64);
    }

    // ---- 2. Pose -> R|t (thread 0), overlapped with the loads in flight. --
    if (threadIdx.x == 0) {
        float tx = pose[0], ty = pose[1], tz = pose[2];
        float px = pose[3], py = pose[4], pz = pose[5];
        float th2 = px * px + py * py + pz * pz;
        float A, B, C;
        if (th2 < 1e-8f) {
            A = 1.0f - th2 / 6.0f;
            B = 0.5f - th2 / 24.0f;
            C = 1.0f / 6.0f - th2 / 120.0f;
        } else {
            float th = sqrtf(th2);
            float s = sinf(th), cs = cosf(th);
            A = s / th;
            B = (1.0f - cs) / th2;
            C = (th - s) / (th2 * th);
        }
        // Phi^2 = phi*phi^T - th2*I (skew-symmetric identity)
        sRt[0] = 1.0f + B * (px * px - th2);
        sRt[1] = -A * pz + B * px * py;
        sRt[2] =  A * py + B * px * pz;
        sRt[3] =  A * pz + B * px * py;
        sRt[4] = 1.0f + B * (py * py - th2);
        sRt[5] = -A * px + B * py * pz;
        sRt[6] = -A * py + B * px * pz;
        sRt[7] =  A * px + B * py * pz;
        sRt[8] = 1.0f + B * (pz * pz - th2);

        float V0 = 1.0f + C * (px * px - th2);
        float V1 = -B * pz + C * px * py;
        float V2 =  B * py + C * px * pz;
        float V3 =  B * pz + C * px * py;
        float V4 = 1.0f + C * (py * py - th2);
        float V5 = -B * px + C * py * pz;
        float V6 = -B * py + C * px * pz;
        float V7 =  B * px + C * py * pz;
        float V8v = 1.0f + C * (pz * pz - th2);

        sRt[9]  = V0 * tx + V1 * ty + V2 * tz;
        sRt[10] = V3 * tx + V4 * ty + V5 * tz;
        sRt[11] = V6 * tx + V7 * ty + V8v * tz;
    }
    __syncthreads();

    float Rt[12];
    #pragma unroll
    for (int k = 0; k < 12; k++) Rt[k] = sRt[k];

    // ---- 3. Transform + store. ----
    if (body) {
        float f[24] = {
            __uint_as_float(a.r0), __uint_as_float(a.r1), __uint_as_float(a.r2),
            __uint_as_float(a.r3), __uint_as_float(a.r4), __uint_as_float(a.r5),
            __uint_as_float(a.r6), __uint_as_float(a.r7),
            __uint_as_float(b.r0), __uint_as_float(b.r1), __uint_as_float(b.r2),
            __uint_as_float(b.r3), __uint_as_float(b.r4), __uint_as_float(b.r5),
            __uint_as_float(b.r6), __uint_as_float(b.r7),
            __uint_as_float(c.r0), __uint_as_float(c.r1), __uint_as_float(c.r2),
            __uint_as_float(c.r3), __uint_as_float(c.r4), __uint_as_float(c.r5),
            __uint_as_float(c.r6), __uint_as_float(c.r7)
        };

        float g[24];
        #pragma unroll
        for (int k = 0; k < 8; k++) {
            float X = f[3 * k], Y = f[3 * k + 1], Z = f[3 * k + 2];
            g[3 * k + 0] = fmaf(Rt[0], X, fmaf(Rt[1], Y, fmaf(Rt[2], Z, Rt[9])));
            g[3 * k + 1] = fmaf(Rt[3], X, fmaf(Rt[4], Y, fmaf(Rt[5], Z, Rt[10])));
            g[3 * k + 2] = fmaf(Rt[6], X, fmaf(Rt[7], Y, fmaf(Rt[8], Z, Rt[11])));
        }

        char* q = ob + (size_t)96 * i;
        stg256_ef(q,      g);
        stg256_ef(q + 32, g + 8);
        stg256_ef(q + 64, g + 16);
    } else if (i == n_oct && n_tail > 0) {
        // Scalar tail (N % 8 points); dead for N = 8388608 but kept general.
        for (int k = 0; k < n_tail; k++) {
            int base = (n_oct * 8 + k) * 3;
            float X = x_tail[base + 0], Y = x_tail[base + 1],
                  Z = x_tail[base + 2];
            o_tail[base + 0] = fmaf(Rt[0], X, fmaf(Rt[1], Y, fmaf(Rt[2], Z, Rt[9])));
            o_tail[base + 1] = fmaf(Rt[3], X, fmaf(Rt[4], Y, fmaf(Rt[5], Z, Rt[10])));
            o_tail[base + 2] = fmaf(Rt[6], X, fmaf(Rt[7], Y, fmaf(Rt[8], Z, Rt[11])));
        }
    }
}

// ---------------------------------------------------------------------------
// Launch: single fused kernel, flat one-shot grid of 128-thread blocks.
// ---------------------------------------------------------------------------
extern "C" void kernel_launch(void* const* d_in, const int* in_sizes, int n_in,
                              void* d_out, int out_size) {
    const float* pose = (const float*)d_in[0];  // (1, 6)
    const float* x    = (const float*)d_in[1];  // (N, 3)
    float* out = (float*)d_out;

    int n_points = in_sizes[1] / 3;
    int n_oct    = n_points / 8;
    int n_tail   = n_points % 8;

    int blocks = (n_oct + 1 + NTHREADS - 1) / NTHREADS;  // +1 thread for tail

    se3_fused_kernel<<<blocks, NTHREADS>>>(
        pose, (const char*)x, (char*)out, n_oct, x, out, n_tail);
}